// round 16
// baseline (speedup 1.0000x reference)
#include <cuda_runtime.h>
#include <cuda_fp16.h>
#include <mma.h>
#include <cfloat>
#include <cstdint>

using namespace nvcuda;

#define BB 8
#define SEQ 4096
#define DIMM 1024
#define MTOT (BB*SEQ)          // 32768
#define QKVN 3072

// ---------------- scratch (allocation-free: __device__ globals) ----------------
static __device__ __align__(1024) __half g_xh   [(size_t)MTOT * DIMM];
static __device__ __align__(1024) __half g_wqkvh[(size_t)QKVN * DIMM];
static __device__ __align__(1024) __half g_wfch [(size_t)DIMM * DIMM];
static __device__ __align__(1024) __half g_Qb   [(size_t)MTOT * DIMM];   // blocked [b,w,i,e]
static __device__ __align__(1024) __half g_Kb   [(size_t)MTOT * DIMM];
static __device__ __align__(1024) __half g_Vb   [(size_t)MTOT * DIMM];
static __device__ __align__(1024) __half g_Ou   [(size_t)MTOT * DIMM];   // un-blocked attn out

__device__ __forceinline__ void cpa16(void* d, const void* s) {
    unsigned u = (unsigned)__cvta_generic_to_shared(d);
    asm volatile("cp.async.cg.shared.global [%0], [%1], 16;" :: "r"(u), "l"(s));
}
__device__ __forceinline__ void cp_commit() { asm volatile("cp.async.commit_group;"); }
__device__ __forceinline__ void cp_wait0()  { asm volatile("cp.async.wait_group 0;"); }
__device__ __forceinline__ void cp_wait1()  { asm volatile("cp.async.wait_group 1;"); }

typedef wmma::fragment<wmma::matrix_a, 16,16,16, __half, wmma::row_major> FragA;
typedef wmma::fragment<wmma::matrix_b, 16,16,16, __half, wmma::col_major> FragBc;
typedef wmma::fragment<wmma::matrix_b, 16,16,16, __half, wmma::row_major> FragBr;
typedef wmma::fragment<wmma::accumulator, 16,16,16, float> FragC;

// ---------------- fp32 -> fp16 converter (all three tensors, one launch) ----------
__global__ void cvt_all_kernel(const float4* __restrict__ x,
                               const float4* __restrict__ wqkv,
                               const float4* __restrict__ wfc) {
    const int stride = gridDim.x * blockDim.x;
    const int tid0 = blockIdx.x * blockDim.x + threadIdx.x;
    {
        __half2* dst = (__half2*)g_xh;
        const int n4 = (int)((size_t)MTOT * DIMM / 4);
        for (int i = tid0; i < n4; i += stride) {
            float4 v = x[i];
            dst[2*i]   = __floats2half2_rn(v.x, v.y);
            dst[2*i+1] = __floats2half2_rn(v.z, v.w);
        }
    }
    {
        __half2* dst = (__half2*)g_wqkvh;
        const int n4 = QKVN * DIMM / 4;
        for (int i = tid0; i < n4; i += stride) {
            float4 v = wqkv[i];
            dst[2*i]   = __floats2half2_rn(v.x, v.y);
            dst[2*i+1] = __floats2half2_rn(v.z, v.w);
        }
    }
    {
        __half2* dst = (__half2*)g_wfch;
        const int n4 = DIMM * DIMM / 4;
        for (int i = tid0; i < n4; i += stride) {
            float4 v = wfc[i];
            dst[2*i]   = __floats2half2_rn(v.x, v.y);
            dst[2*i+1] = __floats2half2_rn(v.z, v.w);
        }
    }
}

// ---------------- HMMA GEMM (R12-proven, frozen): CTA 128x128, BK=64, 3-stage -------
#define G_STG   36864            // (128+128)*72*2 bytes per stage
#define G_AOFF  18432            // A part: 128*72*2
#define G_KS    16               // 1024/64 k-steps

template<int MODE>
__global__ __launch_bounds__(256) void gemm2_kernel(float* __restrict__ outp,
                                                    const float* __restrict__ bias) {
    extern __shared__ char sm[];
    const int tid  = threadIdx.x;
    const int warp = tid >> 5;
    const int wm = warp & 3, wn = warp >> 2;
    const int m0 = blockIdx.y << 7;
    const int j0 = blockIdx.x << 7;

    const __half* Ag = (MODE == 0 ? g_xh    : g_Ou)   + (size_t)m0 * DIMM;
    const __half* Bg = (MODE == 0 ? g_wqkvh : g_wfch) + (size_t)j0 * DIMM;

    FragC acc[2][4];
    #pragma unroll
    for (int mi = 0; mi < 2; ++mi)
        #pragma unroll
        for (int ni = 0; ni < 4; ++ni) wmma::fill_fragment(acc[mi][ni], 0.0f);

    auto load_stage = [&](int kt) {
        char* st = sm + (kt % 3) * G_STG;
        const int k0 = kt << 6;
        #pragma unroll
        for (int r = 0; r < 4; ++r) {
            int q = tid + (r << 8);
            int row = q >> 3, off = q & 7;
            cpa16((__half*)st + row*72 + off*8, Ag + (size_t)row*DIMM + k0 + off*8);
        }
        #pragma unroll
        for (int r = 0; r < 4; ++r) {
            int q = tid + (r << 8);
            int row = q >> 3, off = q & 7;
            cpa16((__half*)(st + G_AOFF) + row*72 + off*8, Bg + (size_t)row*DIMM + k0 + off*8);
        }
    };

    load_stage(0); cp_commit();
    load_stage(1); cp_commit();

    for (int kt = 0; kt < G_KS; ++kt) {
        cp_wait1();
        __syncthreads();
        if (kt + 2 < G_KS) { load_stage(kt + 2); cp_commit(); }
        else               { cp_commit(); }
        const __half* As = (const __half*)(sm + (kt % 3) * G_STG);
        const __half* Bs = (const __half*)(sm + (kt % 3) * G_STG + G_AOFF);
        #pragma unroll
        for (int kk = 0; kk < 4; ++kk) {
            FragA af[2];
            #pragma unroll
            for (int mi = 0; mi < 2; ++mi)
                wmma::load_matrix_sync(af[mi], As + (wm*32 + mi*16)*72 + kk*16, 72);
            #pragma unroll
            for (int ni = 0; ni < 4; ++ni) {
                FragBc bf;
                wmma::load_matrix_sync(bf, Bs + (wn*64 + ni*16)*72 + kk*16, 72);
                #pragma unroll
                for (int mi = 0; mi < 2; ++mi)
                    wmma::mma_sync(acc[mi][ni], af[mi], bf, acc[mi][ni]);
            }
        }
    }
    cp_wait0();
    __syncthreads();

    float* Cs = (float*)sm;
    #pragma unroll
    for (int mi = 0; mi < 2; ++mi)
        #pragma unroll
        for (int ni = 0; ni < 4; ++ni)
            wmma::store_matrix_sync(Cs + (wm*32 + mi*16)*132 + wn*64 + ni*16,
                                    acc[mi][ni], 132, wmma::mem_row_major);
    __syncthreads();
    if (MODE == 0) {
        for (int idx = tid; idx < 8192; idx += 256) {
            int r  = idx >> 6;
            int cc = (idx & 63) << 1;
            float v0 = Cs[r*132 + cc];
            float v1 = Cs[r*132 + cc + 1];
            int m = m0 + r, j = j0 + cc;
            int b = m >> 12, n = m & 4095;
            int which = j >> 10, c = j & 1023;
            int h = c >> 6, dh = c & 63;
            int wv = (h << 1) + (n >> 11);
            int iw = (n >> 4) & 127;
            int e  = ((n & 15) << 6) | dh;
            size_t dst = ((((size_t)b * 32 + wv) * 128 + iw) << 10) + (size_t)e;
            __half* base = (which == 0) ? g_Qb : (which == 1) ? g_Kb : g_Vb;
            *(__half2*)(base + dst) = __floats2half2_rn(v0, v1);
        }
    } else {
        for (int idx = tid; idx < 4096; idx += 256) {
            int r = idx >> 5, q = (idx & 31) << 2;
            int m = m0 + r, j = j0 + q;
            float4 bv = *(const float4*)&bias[j];
            float4 v;
            v.x = Cs[r*132 + q]     + bv.x;
            v.y = Cs[r*132 + q + 1] + bv.y;
            v.z = Cs[r*132 + q + 2] + bv.z;
            v.w = Cs[r*132 + q + 3] + bv.w;
            *(float4*)&outp[(size_t)m * DIMM + j] = v;
        }
    }
}

// ---------------- Attention: deep-pipelined. Per (b,w) full 128-row tile ------------
// smem layout (217088 B peak) — Ps past BOTH V stages (overlap-free):
//   QK phase : 3 stages x 55296 at 0           [0, 165888)
//   Ss  f32  [128][264] at 0                   [0, 135168)   (after QK drained)
//   PV  Vs   : 2 stages x 69632 at 0           [0, 139264)   (Ss dead by then)
//   Ps  half [128][264] at 139264              [139264, 206848)
//   warp bufs: 8 x 1280 at 206848              [206848, 217088)
#define AT_PS    139264
#define AT_WBUF  206848
#define AT_SMEM  217088

__global__ __launch_bounds__(256) void attn_kernel(float* __restrict__ attn_out) {
    extern __shared__ char smraw[];
    const int bw = blockIdx.x;
    const int b = bw >> 5, w = bw & 31;
    const int tid = threadIdx.x;
    const int warp = tid >> 5, lane = tid & 31;
    const int bwlo = (w > 0) ? (bw - 1) : bw;

    const __half* Qg  = g_Qb + ((size_t)bw   << 17);
    const __half* Klo = g_Kb + ((size_t)bwlo << 17);
    const __half* Khi = g_Kb + ((size_t)bw   << 17);

    const int wm = warp & 3, wj = warp >> 2;

    FragC acc[2][8];
    #pragma unroll
    for (int mi = 0; mi < 2; ++mi)
        #pragma unroll
        for (int ji = 0; ji < 8; ++ji) wmma::fill_fragment(acc[mi][ji], 0.0f);

    auto load_qk = [&](int et) {
        __half* Qs = (__half*)(smraw + (et % 3) * 55296);
        __half* Ks = Qs + 9216;   // 18432 B after Qs start
        const int e0 = et << 6;
        #pragma unroll
        for (int r = 0; r < 4; ++r) {
            int q = tid + (r << 8);
            int row = q >> 3, off = q & 7;
            cpa16(Qs + row*72 + off*8, Qg + ((size_t)row << 10) + e0 + off*8);
        }
        #pragma unroll
        for (int r = 0; r < 8; ++r) {
            int q = tid + (r << 8);
            int j = q >> 3, off = q & 7;
            const __half* src = (j < 128) ? (Klo + ((size_t)j << 10))
                                          : (Khi + ((size_t)(j - 128) << 10));
            cpa16(Ks + j*72 + off*8, src + e0 + off*8);
        }
    };

    // ---- QK^T mainloop: 3-stage, wait_group 1 (one stage lookahead) ----
    load_qk(0); cp_commit();
    load_qk(1); cp_commit();
    for (int et = 0; et < 16; ++et) {
        cp_wait1();
        __syncthreads();
        if (et + 2 < 16) { load_qk(et + 2); cp_commit(); }
        else             { cp_commit(); }
        const __half* Qs = (const __half*)(smraw + (et % 3) * 55296);
        const __half* Ks = Qs + 9216;
        #pragma unroll
        for (int kk = 0; kk < 4; ++kk) {
            FragA af[2];
            #pragma unroll
            for (int mi = 0; mi < 2; ++mi)
                wmma::load_matrix_sync(af[mi], Qs + (wm*32 + mi*16)*72 + kk*16, 72);
            #pragma unroll
            for (int ji = 0; ji < 8; ++ji) {
                FragBc bf;
                wmma::load_matrix_sync(bf, Ks + (wj*128 + ji*16)*72 + kk*16, 72);
                #pragma unroll
                for (int mi = 0; mi < 2; ++mi)
                    wmma::mma_sync(acc[mi][ji], af[mi], bf, acc[mi][ji]);
            }
        }
    }
    cp_wait0();
    __syncthreads();

    float* Ss = (float*)smraw;
    #pragma unroll
    for (int mi = 0; mi < 2; ++mi)
        #pragma unroll
        for (int ji = 0; ji < 8; ++ji)
            wmma::store_matrix_sync(Ss + (wm*32 + mi*16)*264 + wj*128 + ji*16,
                                    acc[mi][ji], 264, wmma::mem_row_major);
    __syncthreads();

    // ---- masked softmax: 16 rows/warp ----
    __half* Ps = (__half*)(smraw + AT_PS);
    const float scale = 0.03125f;
    float* arow = attn_out ? (attn_out + ((size_t)bw << 15)) : (float*)0;
    for (int rr = 0; rr < 16; ++rr) {
        const int i = warp + (rr << 3);
        float vals[8];
        float mx = -FLT_MAX;
        #pragma unroll
        for (int t = 0; t < 8; ++t) {
            const int j = lane + (t << 5);
            const bool valid = (j >= 128) ? ((j - 128) <= i) : (w > 0);
            float s = valid ? (Ss[i*264 + j] * scale) : -FLT_MAX;
            vals[t] = s;
            mx = fmaxf(mx, s);
        }
        #pragma unroll
        for (int o = 16; o > 0; o >>= 1) mx = fmaxf(mx, __shfl_xor_sync(0xffffffffu, mx, o));
        float sum = 0.f;
        #pragma unroll
        for (int t = 0; t < 8; ++t) {
            const int j = lane + (t << 5);
            const bool valid = (j >= 128) ? ((j - 128) <= i) : (w > 0);
            float e = valid ? __expf(vals[t] - mx) : 0.f;
            vals[t] = e;
            sum += e;
        }
        #pragma unroll
        for (int o = 16; o > 0; o >>= 1) sum += __shfl_xor_sync(0xffffffffu, sum, o);
        const float inv = 1.0f / sum;
        #pragma unroll
        for (int t = 0; t < 8; ++t) {
            const int j = lane + (t << 5);
            const float p = vals[t] * inv;
            Ps[i*264 + j] = __float2half_rn(p);
            if (arow) arow[((size_t)i << 8) + j] = p;
        }
    }
    __syncthreads();

    // ---- O = P @ V: 8 e-chunks, double-buffered Vs, per-warp fragment scatter ----
    const __half* Vlo = g_Vb + ((size_t)bwlo << 17);
    const __half* Vhi = g_Vb + ((size_t)bw   << 17);
    float* buf = (float*)(smraw + AT_WBUF + warp * 1280);
    const int wn = warp >> 2;
    const int h = w >> 1;
    const int nbase = (b << 12) | ((w & 1) << 11);

    auto load_v = [&](int cc) {
        __half* Vs = (__half*)(smraw + (cc & 1) * 69632);
        #pragma unroll
        for (int r = 0; r < 16; ++r) {
            int q = tid + (r << 8);
            int j = q >> 4, off = q & 15;
            const __half* src = (j < 128) ? (Vlo + ((size_t)j << 10))
                                          : (Vhi + ((size_t)(j - 128) << 10));
            cpa16(Vs + j*136 + off*8, src + (cc << 7) + off*8);
        }
    };

    load_v(0); cp_commit();
    #pragma unroll 1
    for (int cc = 0; cc < 8; ++cc) {
        __syncthreads();                       // all warps done reading stage (cc-1)&1
        if (cc + 1 < 8) { load_v(cc + 1); cp_commit(); }
        else            { cp_commit(); }
        cp_wait1();                            // stage cc complete
        __syncthreads();                       // cp.async visibility across warps
        const __half* Vs = (const __half*)(smraw + (cc & 1) * 69632);
        FragC oacc[2][4];
        #pragma unroll
        for (int mi = 0; mi < 2; ++mi)
            #pragma unroll
            for (int ni = 0; ni < 4; ++ni) wmma::fill_fragment(oacc[mi][ni], 0.0f);
        #pragma unroll
        for (int kk = 0; kk < 16; ++kk) {
            FragA af[2];
            #pragma unroll
            for (int mi = 0; mi < 2; ++mi)
                wmma::load_matrix_sync(af[mi], Ps + (wm*32 + mi*16)*264 + kk*16, 264);
            #pragma unroll
            for (int ni = 0; ni < 4; ++ni) {
                FragBr bf;
                wmma::load_matrix_sync(bf, Vs + (kk*16)*136 + wn*64 + ni*16, 136);
                #pragma unroll
                for (int mi = 0; mi < 2; ++mi)
                    wmma::mma_sync(oacc[mi][ni], af[mi], bf, oacc[mi][ni]);
            }
        }
        // per-warp fragment scatter (no CTA barrier)
        #pragma unroll 1
        for (int mi = 0; mi < 2; ++mi) {
            #pragma unroll 1
            for (int ni = 0; ni < 4; ++ni) {
                wmma::store_matrix_sync(buf, oacc[mi][ni], 20, wmma::mem_row_major);
                __syncwarp();
                #pragma unroll
                for (int i = 0; i < 4; ++i) {
                    int p = lane + (i << 5);
                    int row = p >> 3, cp2 = p & 7;
                    float v0 = buf[row*20 + cp2*2];
                    float v1 = buf[row*20 + cp2*2 + 1];
                    int rg = wm*32 + mi*16 + row;
                    int e  = (cc << 7) + wn*64 + ni*16 + cp2*2;
                    int t = e >> 6, dh = e & 63;
                    int n = nbase + (rg << 4) + t;
                    size_t dst = (((size_t)n) << 10) + (size_t)((h << 6) | dh);
                    *(__half2*)(g_Ou + dst) = __floats2half2_rn(v0, v1);
                }
                __syncwarp();
            }
        }
    }
}

// ---------------- launch ----------------
extern "C" void kernel_launch(void* const* d_in, const int* in_sizes, int n_in,
                              void* d_out, int out_size) {
    const float* x     = (const float*)d_in[0];
    const float* w_qkv = (const float*)d_in[2];
    const float* w_fc  = (const float*)d_in[3];
    const float* b_fc  = (const float*)d_in[4];

    float* out  = (float*)d_out;
    float* attn = (out_size >= 33554432 + 8388608) ? (out + 33554432) : (float*)0;

    const int G_SMEM = 3 * G_STG;   // 110592
    cudaFuncSetAttribute(gemm2_kernel<0>, cudaFuncAttributeMaxDynamicSharedMemorySize, G_SMEM);
    cudaFuncSetAttribute(gemm2_kernel<1>, cudaFuncAttributeMaxDynamicSharedMemorySize, G_SMEM);
    cudaFuncSetAttribute(attn_kernel,     cudaFuncAttributeMaxDynamicSharedMemorySize, AT_SMEM);

    cvt_all_kernel<<<4096, 256>>>((const float4*)x, (const float4*)w_qkv, (const float4*)w_fc);
    gemm2_kernel<0><<<dim3(24, 256), 256, G_SMEM>>>((float*)0, (const float*)0);
    attn_kernel<<<256, 256, AT_SMEM>>>(attn);
    gemm2_kernel<1><<<dim3(8, 256), 256, G_SMEM>>>(out, b_fc);
}

// round 17
// speedup vs baseline: 1.0600x; 1.0600x over previous
#include <cuda_runtime.h>
#include <cuda_fp16.h>
#include <mma.h>
#include <cfloat>
#include <cstdint>

using namespace nvcuda;

#define BB 8
#define SEQ 4096
#define DIMM 1024
#define MTOT (BB*SEQ)          // 32768
#define QKVN 3072

// ---------------- scratch (allocation-free: __device__ globals) ----------------
static __device__ __align__(1024) __half g_xh   [(size_t)MTOT * DIMM];
static __device__ __align__(1024) __half g_wqkvh[(size_t)QKVN * DIMM];
static __device__ __align__(1024) __half g_wfch [(size_t)DIMM * DIMM];
static __device__ __align__(1024) __half g_Qb   [(size_t)MTOT * DIMM];   // blocked [b,w,i,e]
static __device__ __align__(1024) __half g_Kb   [(size_t)MTOT * DIMM];
static __device__ __align__(1024) __half g_Vb   [(size_t)MTOT * DIMM];
static __device__ __align__(1024) __half g_Ou   [(size_t)MTOT * DIMM];   // un-blocked attn out

__device__ __forceinline__ void cpa16(void* d, const void* s) {
    unsigned u = (unsigned)__cvta_generic_to_shared(d);
    asm volatile("cp.async.cg.shared.global [%0], [%1], 16;" :: "r"(u), "l"(s));
}
__device__ __forceinline__ void cp_commit() { asm volatile("cp.async.commit_group;"); }
__device__ __forceinline__ void cp_wait0()  { asm volatile("cp.async.wait_group 0;"); }
__device__ __forceinline__ void cp_wait1()  { asm volatile("cp.async.wait_group 1;"); }

typedef wmma::fragment<wmma::matrix_a, 16,16,16, __half, wmma::row_major> FragA;
typedef wmma::fragment<wmma::matrix_b, 16,16,16, __half, wmma::col_major> FragBc;
typedef wmma::fragment<wmma::matrix_b, 16,16,16, __half, wmma::row_major> FragBr;
typedef wmma::fragment<wmma::accumulator, 16,16,16, float> FragC;

// ---------------- fp32 -> fp16 converter (all three tensors, one launch) ----------
__global__ void cvt_all_kernel(const float4* __restrict__ x,
                               const float4* __restrict__ wqkv,
                               const float4* __restrict__ wfc) {
    const int stride = gridDim.x * blockDim.x;
    const int tid0 = blockIdx.x * blockDim.x + threadIdx.x;
    {
        __half2* dst = (__half2*)g_xh;
        const int n4 = (int)((size_t)MTOT * DIMM / 4);
        for (int i = tid0; i < n4; i += stride) {
            float4 v = x[i];
            dst[2*i]   = __floats2half2_rn(v.x, v.y);
            dst[2*i+1] = __floats2half2_rn(v.z, v.w);
        }
    }
    {
        __half2* dst = (__half2*)g_wqkvh;
        const int n4 = QKVN * DIMM / 4;
        for (int i = tid0; i < n4; i += stride) {
            float4 v = wqkv[i];
            dst[2*i]   = __floats2half2_rn(v.x, v.y);
            dst[2*i+1] = __floats2half2_rn(v.z, v.w);
        }
    }
    {
        __half2* dst = (__half2*)g_wfch;
        const int n4 = DIMM * DIMM / 4;
        for (int i = tid0; i < n4; i += stride) {
            float4 v = wfc[i];
            dst[2*i]   = __floats2half2_rn(v.x, v.y);
            dst[2*i+1] = __floats2half2_rn(v.z, v.w);
        }
    }
}

// ---------------- HMMA GEMM: CTA 128x128, BK=64, 3-stage, single barrier ------------
// 8 warps (4m x 2n), warp tile 32x64. B-fragment double-buffered in the ni loop
// (bf[2], +8 regs vs R12's 100 -> ~108, still 2 CTAs/SM; LB(256,2) pins it).
#define G_STG   36864            // (128+128)*72*2 bytes per stage
#define G_AOFF  18432            // A part: 128*72*2
#define G_KS    16               // 1024/64 k-steps

template<int MODE>
__global__ __launch_bounds__(256, 2) void gemm2_kernel(float* __restrict__ outp,
                                                       const float* __restrict__ bias) {
    extern __shared__ char sm[];
    const int tid  = threadIdx.x;
    const int warp = tid >> 5;
    const int wm = warp & 3, wn = warp >> 2;
    const int m0 = blockIdx.y << 7;
    const int j0 = blockIdx.x << 7;

    const __half* Ag = (MODE == 0 ? g_xh    : g_Ou)   + (size_t)m0 * DIMM;
    const __half* Bg = (MODE == 0 ? g_wqkvh : g_wfch) + (size_t)j0 * DIMM;

    FragC acc[2][4];
    #pragma unroll
    for (int mi = 0; mi < 2; ++mi)
        #pragma unroll
        for (int ni = 0; ni < 4; ++ni) wmma::fill_fragment(acc[mi][ni], 0.0f);

    auto load_stage = [&](int kt) {
        char* st = sm + (kt % 3) * G_STG;
        const int k0 = kt << 6;
        #pragma unroll
        for (int r = 0; r < 4; ++r) {
            int q = tid + (r << 8);
            int row = q >> 3, off = q & 7;
            cpa16((__half*)st + row*72 + off*8, Ag + (size_t)row*DIMM + k0 + off*8);
        }
        #pragma unroll
        for (int r = 0; r < 4; ++r) {
            int q = tid + (r << 8);
            int row = q >> 3, off = q & 7;
            cpa16((__half*)(st + G_AOFF) + row*72 + off*8, Bg + (size_t)row*DIMM + k0 + off*8);
        }
    };

    load_stage(0); cp_commit();
    load_stage(1); cp_commit();

    for (int kt = 0; kt < G_KS; ++kt) {
        cp_wait1();
        __syncthreads();
        if (kt + 2 < G_KS) { load_stage(kt + 2); cp_commit(); }
        else               { cp_commit(); }
        const __half* As = (const __half*)(sm + (kt % 3) * G_STG);
        const __half* Bs = (const __half*)(sm + (kt % 3) * G_STG + G_AOFF);
        #pragma unroll
        for (int kk = 0; kk < 4; ++kk) {
            FragA af[2];
            #pragma unroll
            for (int mi = 0; mi < 2; ++mi)
                wmma::load_matrix_sync(af[mi], As + (wm*32 + mi*16)*72 + kk*16, 72);
            FragBc bf[2];
            wmma::load_matrix_sync(bf[0], Bs + (wn*64)*72 + kk*16, 72);
            #pragma unroll
            for (int ni = 0; ni < 4; ++ni) {
                if (ni < 3)
                    wmma::load_matrix_sync(bf[(ni+1)&1], Bs + (wn*64 + (ni+1)*16)*72 + kk*16, 72);
                #pragma unroll
                for (int mi = 0; mi < 2; ++mi)
                    wmma::mma_sync(acc[mi][ni], af[mi], bf[ni&1], acc[mi][ni]);
            }
        }
    }
    cp_wait0();
    __syncthreads();

    float* Cs = (float*)sm;
    #pragma unroll
    for (int mi = 0; mi < 2; ++mi)
        #pragma unroll
        for (int ni = 0; ni < 4; ++ni)
            wmma::store_matrix_sync(Cs + (wm*32 + mi*16)*132 + wn*64 + ni*16,
                                    acc[mi][ni], 132, wmma::mem_row_major);
    __syncthreads();
    if (MODE == 0) {
        for (int idx = tid; idx < 8192; idx += 256) {
            int r  = idx >> 6;
            int cc = (idx & 63) << 1;
            float v0 = Cs[r*132 + cc];
            float v1 = Cs[r*132 + cc + 1];
            int m = m0 + r, j = j0 + cc;
            int b = m >> 12, n = m & 4095;
            int which = j >> 10, c = j & 1023;
            int h = c >> 6, dh = c & 63;
            int wv = (h << 1) + (n >> 11);
            int iw = (n >> 4) & 127;
            int e  = ((n & 15) << 6) | dh;
            size_t dst = ((((size_t)b * 32 + wv) * 128 + iw) << 10) + (size_t)e;
            __half* base = (which == 0) ? g_Qb : (which == 1) ? g_Kb : g_Vb;
            *(__half2*)(base + dst) = __floats2half2_rn(v0, v1);
        }
    } else {
        for (int idx = tid; idx < 4096; idx += 256) {
            int r = idx >> 5, q = (idx & 31) << 2;
            int m = m0 + r, j = j0 + q;
            float4 bv = *(const float4*)&bias[j];
            float4 v;
            v.x = Cs[r*132 + q]     + bv.x;
            v.y = Cs[r*132 + q + 1] + bv.y;
            v.z = Cs[r*132 + q + 2] + bv.z;
            v.w = Cs[r*132 + q + 3] + bv.w;
            *(float4*)&outp[(size_t)m * DIMM + j] = v;
        }
    }
}

// ---------------- Attention (R12-measured best, restored verbatim) ------------------
__global__ __launch_bounds__(256) void attn_kernel(float* __restrict__ attn_out) {
    extern __shared__ char smraw[];
    const int bw = blockIdx.x;
    const int b = bw >> 5, w = bw & 31;
    const int tid = threadIdx.x;
    const int warp = tid >> 5, lane = tid & 31;
    const int bwlo = (w > 0) ? (bw - 1) : bw;

    const __half* Qg  = g_Qb + ((size_t)bw   << 17);
    const __half* Klo = g_Kb + ((size_t)bwlo << 17);
    const __half* Khi = g_Kb + ((size_t)bw   << 17);

    const int wm = warp & 3, wj = warp >> 2;

    FragC acc[2][8];
    #pragma unroll
    for (int mi = 0; mi < 2; ++mi)
        #pragma unroll
        for (int ji = 0; ji < 8; ++ji) wmma::fill_fragment(acc[mi][ji], 0.0f);

    auto load_qk = [&](int et, int s) {
        __half* Qs = (__half*)(smraw + s * 55296);
        __half* Ks = (__half*)(smraw + s * 55296 + 18432);
        const int e0 = et << 6;
        #pragma unroll
        for (int r = 0; r < 4; ++r) {
            int q = tid + (r << 8);
            int row = q >> 3, off = q & 7;
            cpa16(Qs + row*72 + off*8, Qg + ((size_t)row << 10) + e0 + off*8);
        }
        #pragma unroll
        for (int r = 0; r < 8; ++r) {
            int q = tid + (r << 8);
            int j = q >> 3, off = q & 7;
            const __half* src = (j < 128) ? (Klo + ((size_t)j << 10))
                                          : (Khi + ((size_t)(j - 128) << 10));
            cpa16(Ks + j*72 + off*8, src + e0 + off*8);
        }
    };

    load_qk(0, 0); cp_commit();
    for (int et = 0; et < 16; ++et) {
        cp_wait0();
        __syncthreads();
        if (et + 1 < 16) { load_qk(et + 1, (et + 1) & 1); cp_commit(); }
        const __half* Qs = (const __half*)(smraw + (et & 1) * 55296);
        const __half* Ks = (const __half*)(smraw + (et & 1) * 55296 + 18432);
        #pragma unroll
        for (int kk = 0; kk < 4; ++kk) {
            FragA af[2];
            #pragma unroll
            for (int mi = 0; mi < 2; ++mi)
                wmma::load_matrix_sync(af[mi], Qs + (wm*32 + mi*16)*72 + kk*16, 72);
            #pragma unroll
            for (int ji = 0; ji < 8; ++ji) {
                FragBc bf;
                wmma::load_matrix_sync(bf, Ks + (wj*128 + ji*16)*72 + kk*16, 72);
                #pragma unroll
                for (int mi = 0; mi < 2; ++mi)
                    wmma::mma_sync(acc[mi][ji], af[mi], bf, acc[mi][ji]);
            }
        }
    }
    __syncthreads();
    float* Ss = (float*)smraw;
    #pragma unroll
    for (int mi = 0; mi < 2; ++mi)
        #pragma unroll
        for (int ji = 0; ji < 8; ++ji)
            wmma::store_matrix_sync(Ss + (wm*32 + mi*16)*264 + wj*128 + ji*16,
                                    acc[mi][ji], 264, wmma::mem_row_major);
    __syncthreads();

    __half* Ps = (__half*)(smraw + 137216);
    const float scale = 0.03125f;
    float* arow = attn_out ? (attn_out + ((size_t)bw << 15)) : (float*)0;
    for (int rr = 0; rr < 16; ++rr) {
        const int i = warp + (rr << 3);
        float vals[8];
        float mx = -FLT_MAX;
        #pragma unroll
        for (int t = 0; t < 8; ++t) {
            const int j = lane + (t << 5);
            const bool valid = (j >= 128) ? ((j - 128) <= i) : (w > 0);
            float s = valid ? (Ss[i*264 + j] * scale) : -FLT_MAX;
            vals[t] = s;
            mx = fmaxf(mx, s);
        }
        #pragma unroll
        for (int o = 16; o > 0; o >>= 1) mx = fmaxf(mx, __shfl_xor_sync(0xffffffffu, mx, o));
        float sum = 0.f;
        #pragma unroll
        for (int t = 0; t < 8; ++t) {
            const int j = lane + (t << 5);
            const bool valid = (j >= 128) ? ((j - 128) <= i) : (w > 0);
            float e = valid ? __expf(vals[t] - mx) : 0.f;
            vals[t] = e;
            sum += e;
        }
        #pragma unroll
        for (int o = 16; o > 0; o >>= 1) sum += __shfl_xor_sync(0xffffffffu, sum, o);
        const float inv = 1.0f / sum;
        #pragma unroll
        for (int t = 0; t < 8; ++t) {
            const int j = lane + (t << 5);
            const float p = vals[t] * inv;
            Ps[i*264 + j] = __float2half_rn(p);
            if (arow) arow[((size_t)i << 8) + j] = p;
        }
    }
    __syncthreads();

    const __half* Vlo = g_Vb + ((size_t)bwlo << 17);
    const __half* Vhi = g_Vb + ((size_t)bw   << 17);
    __half* Vs = (__half*)smraw;
    float* Os = (float*)(smraw + 69632);
    const int wn = warp >> 2;
    const int h = w >> 1;
    const int nbase = (b << 12) | ((w & 1) << 11);
    for (int cc = 0; cc < 8; ++cc) {
        #pragma unroll
        for (int r = 0; r < 16; ++r) {
            int q = tid + (r << 8);
            int j = q >> 4, off = q & 15;
            const __half* src = (j < 128) ? (Vlo + ((size_t)j << 10))
                                          : (Vhi + ((size_t)(j - 128) << 10));
            cpa16(Vs + j*136 + off*8, src + (cc << 7) + off*8);
        }
        cp_commit(); cp_wait0();
        __syncthreads();
        FragC oacc[2][4];
        #pragma unroll
        for (int mi = 0; mi < 2; ++mi)
            #pragma unroll
            for (int ni = 0; ni < 4; ++ni) wmma::fill_fragment(oacc[mi][ni], 0.0f);
        #pragma unroll
        for (int kk = 0; kk < 16; ++kk) {
            FragA af[2];
            #pragma unroll
            for (int mi = 0; mi < 2; ++mi)
                wmma::load_matrix_sync(af[mi], Ps + (wm*32 + mi*16)*264 + kk*16, 264);
            #pragma unroll
            for (int ni = 0; ni < 4; ++ni) {
                FragBr bf;
                wmma::load_matrix_sync(bf, Vs + (kk*16)*136 + wn*64 + ni*16, 136);
                #pragma unroll
                for (int mi = 0; mi < 2; ++mi)
                    wmma::mma_sync(oacc[mi][ni], af[mi], bf, oacc[mi][ni]);
            }
        }
        #pragma unroll
        for (int mi = 0; mi < 2; ++mi)
            #pragma unroll
            for (int ni = 0; ni < 4; ++ni)
                wmma::store_matrix_sync(Os + (wm*32 + mi*16)*132 + wn*64 + ni*16,
                                        oacc[mi][ni], 132, wmma::mem_row_major);
        __syncthreads();
        for (int idx = tid; idx < 8192; idx += 256) {
            int r  = idx >> 6;
            int ec = (idx & 63) << 1;
            float v0 = Os[r*132 + ec], v1 = Os[r*132 + ec + 1];
            int e = (cc << 7) + ec;
            int t = e >> 6, dh = e & 63;
            int n = nbase + (r << 4) + t;
            size_t dst = (((size_t)n) << 10) + (h << 6) + dh;
            *(__half2*)(g_Ou + dst) = __floats2half2_rn(v0, v1);
        }
        __syncthreads();
    }
}

// ---------------- launch ----------------
extern "C" void kernel_launch(void* const* d_in, const int* in_sizes, int n_in,
                              void* d_out, int out_size) {
    const float* x     = (const float*)d_in[0];
    const float* w_qkv = (const float*)d_in[2];
    const float* w_fc  = (const float*)d_in[3];
    const float* b_fc  = (const float*)d_in[4];

    float* out  = (float*)d_out;
    float* attn = (out_size >= 33554432 + 8388608) ? (out + 33554432) : (float*)0;

    const int G_SMEM = 3 * G_STG;   // 110592
    cudaFuncSetAttribute(gemm2_kernel<0>, cudaFuncAttributeMaxDynamicSharedMemorySize, G_SMEM);
    cudaFuncSetAttribute(gemm2_kernel<1>, cudaFuncAttributeMaxDynamicSharedMemorySize, G_SMEM);
    cudaFuncSetAttribute(attn_kernel,     cudaFuncAttributeMaxDynamicSharedMemorySize, 204800);

    cvt_all_kernel<<<4096, 256>>>((const float4*)x, (const float4*)w_qkv, (const float4*)w_fc);
    gemm2_kernel<0><<<dim3(24, 256), 256, G_SMEM>>>((float*)0, (const float*)0);
    attn_kernel<<<256, 256, 204800>>>(attn);
    gemm2_kernel<1><<<dim3(8, 256), 256, G_SMEM>>>(out, b_fc);
}